// round 6
// baseline (speedup 1.0000x reference)
#include <cuda_runtime.h>
#include <cuda_bf16.h>
#include <stdint.h>

#define BATCH 2
#define SEQ 2048
#define DM 1024
#define NH 16
#define DH 64
#define MTOT (BATCH*SEQ)
#define QSCALE 0.18033688f   // log2(e) / sqrt(64)

typedef __nv_bfloat16 bf16;

// ---------------- device-global scratch ----------------
__device__ __align__(16) bf16 g_xh[3ull*MTOT*DM], g_xl[3ull*MTOT*DM];
__device__ __align__(16) bf16 g_wth[3ull*DM*DM],  g_wtl[3ull*DM*DM];
__device__ __align__(16) bf16 g_woth[(size_t)DM*DM], g_wotl[(size_t)DM*DM];
__device__ __align__(16) bf16 g_qh[(size_t)MTOT*DM], g_ql[(size_t)MTOT*DM];
__device__ __align__(16) bf16 g_kh[(size_t)MTOT*DM], g_kl[(size_t)MTOT*DM];
__device__ __align__(16) bf16 g_vth[(size_t)MTOT*DM], g_vtl[(size_t)MTOT*DM]; // [bh*64+d][seq]
__device__ __align__(16) bf16 g_zh[(size_t)MTOT*DM], g_zl[(size_t)MTOT*DM];

// ---------------- helpers ----------------
__device__ __forceinline__ uint32_t smem_u32(const void* p) {
    uint32_t a;
    asm("{ .reg .u64 t; cvta.to.shared.u64 t, %1; cvt.u32.u64 %0, t; }" : "=r"(a) : "l"(p));
    return a;
}
#define SWZ128(o) ((o) ^ (((o) >> 3) & 0x70))

__device__ __forceinline__ void mma_bf16(float* c, const uint32_t* a, uint32_t b0, uint32_t b1) {
    asm volatile("mma.sync.aligned.m16n8k16.row.col.f32.bf16.bf16.f32 "
        "{%0,%1,%2,%3}, {%4,%5,%6,%7}, {%8,%9}, {%0,%1,%2,%3};"
        : "+f"(c[0]), "+f"(c[1]), "+f"(c[2]), "+f"(c[3])
        : "r"(a[0]), "r"(a[1]), "r"(a[2]), "r"(a[3]), "r"(b0), "r"(b1));
}
__device__ __forceinline__ void ldsm4(uint32_t* r, uint32_t a) {
    asm volatile("ldmatrix.sync.aligned.m8n8.x4.shared.b16 {%0,%1,%2,%3}, [%4];"
        : "=r"(r[0]), "=r"(r[1]), "=r"(r[2]), "=r"(r[3]) : "r"(a));
}
__device__ __forceinline__ uint32_t fraddr(uint32_t base, int lane, int r0, int ku) {
    int g = lane >> 3, r8 = lane & 7;
    return base + SWZ128(((r0 + r8 + ((g & 1) << 3)) << 7) + ((ku + (g >> 1)) << 4));
}
__device__ __forceinline__ float ex2f(float x) {
    float y; asm("ex2.approx.f32 %0, %1;" : "=f"(y) : "f"(x)); return y;
}
__device__ __forceinline__ void split2(float a, float b, uint32_t& hi, uint32_t& lo) {
    bf16 ah = __float2bfloat16(a), bh = __float2bfloat16(b);
    __nv_bfloat162 H; H.x = ah; H.y = bh;
    __nv_bfloat162 L;
    L.x = __float2bfloat16(a - __bfloat162float(ah));
    L.y = __float2bfloat16(b - __bfloat162float(bh));
    hi = *(uint32_t*)&H; lo = *(uint32_t*)&L;
}
__device__ __forceinline__ void cpa16(uint32_t dst, const void* src) {
    asm volatile("cp.async.cg.shared.global [%0], [%1], 16;" :: "r"(dst), "l"(src) : "memory");
}
#define CP_COMMIT() asm volatile("cp.async.commit_group;" ::: "memory")
#define CP_WAIT(n)  asm volatile("cp.async.wait_group %0;" :: "n"(n) : "memory")

// ---------------- conversion kernels ----------------
__global__ __launch_bounds__(256) void cvt_x_kernel(
    const float* __restrict__ q, const float* __restrict__ k, const float* __restrict__ v) {
    const int z = blockIdx.y;
    const float* __restrict__ src = (z == 0) ? q : (z == 1) ? k : v;
    size_t base = (size_t)z * MTOT * DM;
    size_t i = ((size_t)blockIdx.x * 256 + threadIdx.x) * 8;
    union { bf16 b[8]; uint4 u; } H, L;
    #pragma unroll
    for (int j = 0; j < 8; j += 4) {
        float4 f = *(const float4*)(src + i + j);
        float fv[4] = {f.x, f.y, f.z, f.w};
        #pragma unroll
        for (int q4 = 0; q4 < 4; q4++) {
            bf16 hh = __float2bfloat16(fv[q4]);
            H.b[j + q4] = hh;
            L.b[j + q4] = __float2bfloat16(fv[q4] - __bfloat162float(hh));
        }
    }
    *(uint4*)(g_xh + base + i) = H.u;
    *(uint4*)(g_xl + base + i) = L.u;
}

__global__ __launch_bounds__(256) void cvt_wqkv_kernel(
    const float* __restrict__ wq, const float* __restrict__ wk, const float* __restrict__ wv) {
    __shared__ float s[32][33];
    const int w = blockIdx.z >> 4, hh = blockIdx.z & 15;
    const float* __restrict__ W = ((w == 0) ? wq : (w == 1) ? wk : wv) + (size_t)hh * DM * DH;
    const int k0 = blockIdx.x * 32, e0 = blockIdx.y * 32;
    const int tx = threadIdx.x, ty = threadIdx.y;
    #pragma unroll
    for (int i = 0; i < 4; i++)
        s[ty + 8 * i][tx] = W[(size_t)(k0 + ty + 8 * i) * DH + e0 + tx];
    __syncthreads();
    size_t dbase = (size_t)w * DM * DM;
    #pragma unroll
    for (int i = 0; i < 4; i++) {
        float v = s[tx][ty + 8 * i];
        bf16 hi = __float2bfloat16(v);
        size_t o = dbase + (size_t)(hh * 64 + e0 + ty + 8 * i) * DM + k0 + tx;
        g_wth[o] = hi;
        g_wtl[o] = __float2bfloat16(v - __bfloat162float(hi));
    }
}

__global__ __launch_bounds__(256) void cvt_wo_kernel(const float* __restrict__ W) {
    __shared__ float s[32][33];
    const int k0 = blockIdx.x * 32, d0 = blockIdx.y * 32;
    const int tx = threadIdx.x, ty = threadIdx.y;
    #pragma unroll
    for (int i = 0; i < 4; i++)
        s[ty + 8 * i][tx] = W[(size_t)(k0 + ty + 8 * i) * DM + d0 + tx];
    __syncthreads();
    #pragma unroll
    for (int i = 0; i < 4; i++) {
        float v = s[tx][ty + 8 * i];
        bf16 hi = __float2bfloat16(v);
        size_t o = (size_t)(d0 + ty + 8 * i) * DM + k0 + tx;
        g_woth[o] = hi;
        g_wotl[o] = __float2bfloat16(v - __bfloat162float(hi));
    }
}

// ---------------- split-bf16 GEMM: C[256x128] = X @ Wt^T (+bias) ----------------
// 256 threads (8 warps: 4M x 2N, warp tile 64m x 64n). K-chunk 64.
// Stage 96KB: A_hi@0 A_lo@32K B_hi@64K B_lo@80K. 2 stages = 192KB dynamic.
#define PJ_AH 0
#define PJ_AL 32768
#define PJ_BH 65536
#define PJ_BL 81920
#define PJ_STAGE 98304

__device__ __forceinline__ void proj_copy(
    const bf16* __restrict__ Xh, const bf16* __restrict__ Xl,
    const bf16* __restrict__ Wh, const bf16* __restrict__ Wl,
    uint32_t sb, int st, int m0, int n0, int k0, int t)
{
    #pragma unroll
    for (int u = 0; u < 16; u++) {                   // A: 256 rows, hi+lo
        int idx = u * 256 + t;
        int sp = idx >> 11, row = (idx >> 3) & 255, c = idx & 7;
        uint32_t so = SWZ128((row << 7) + (c << 4));
        cpa16(sb + st + (sp ? PJ_AL : PJ_AH) + so,
              (sp ? Xl : Xh) + (size_t)(m0 + row) * DM + k0 + c * 8);
    }
    #pragma unroll
    for (int u = 0; u < 8; u++) {                    // B: 128 rows, hi+lo
        int idx = u * 256 + t;
        int sp = idx >> 10, row = (idx >> 3) & 127, c = idx & 7;
        uint32_t so = SWZ128((row << 7) + (c << 4));
        cpa16(sb + st + (sp ? PJ_BL : PJ_BH) + so,
              (sp ? Wl : Wh) + (size_t)(n0 + row) * DM + k0 + c * 8);
    }
}

__device__ __forceinline__ void proj_compute(uint32_t sb, int st, int lane,
                                             int wm, int wn, float acc[4][8][4])
{
    #pragma unroll
    for (int ks = 0; ks < 4; ks++) {
        uint32_t aH[4][4], aL[4][4];
        #pragma unroll
        for (int mt = 0; mt < 4; mt++) {
            ldsm4(aH[mt], fraddr(sb + st + PJ_AH, lane, wm + mt * 16, 2 * ks));
            ldsm4(aL[mt], fraddr(sb + st + PJ_AL, lane, wm + mt * 16, 2 * ks));
        }
        #pragma unroll
        for (int np = 0; np < 4; np++) {
            uint32_t bH[4], bL[4];
            ldsm4(bH, fraddr(sb + st + PJ_BH, lane, wn + np * 16, 2 * ks));
            ldsm4(bL, fraddr(sb + st + PJ_BL, lane, wn + np * 16, 2 * ks));
            #pragma unroll
            for (int mt = 0; mt < 4; mt++) {
                mma_bf16(acc[mt][2*np],   aH[mt], bH[0], bH[2]);
                mma_bf16(acc[mt][2*np+1], aH[mt], bH[1], bH[3]);
                mma_bf16(acc[mt][2*np],   aH[mt], bL[0], bL[2]);
                mma_bf16(acc[mt][2*np+1], aH[mt], bL[1], bL[3]);
                mma_bf16(acc[mt][2*np],   aL[mt], bH[0], bH[2]);
                mma_bf16(acc[mt][2*np+1], aL[mt], bH[1], bH[3]);
            }
        }
    }
}

// mode: 0=Q (scale, split out), 1=K (split out), 2=V (transposed split out), 3=fp32 out
__device__ __forceinline__ void proj_core(
    const bf16* __restrict__ Xh, const bf16* __restrict__ Xl,
    const bf16* __restrict__ Wh, const bf16* __restrict__ Wl,
    const float* __restrict__ bias,
    bf16* __restrict__ Oh, bf16* __restrict__ Ol, float* __restrict__ Of,
    char* sm, int m0, int n0, int mode)
{
    const int t = threadIdx.x, lane = t & 31, w = t >> 5;
    const uint32_t sb = smem_u32(sm);
    const int wm = (w & 3) * 64, wn = (w >> 2) * 64;
    float acc[4][8][4] = {};

    proj_copy(Xh, Xl, Wh, Wl, sb, 0, m0, n0, 0, t);
    CP_COMMIT();

    for (int kc = 0; kc < 16; kc++) {
        if (kc + 1 < 16) {
            proj_copy(Xh, Xl, Wh, Wl, sb, ((kc + 1) & 1) * PJ_STAGE, m0, n0, (kc + 1) * 64, t);
            CP_COMMIT();
            CP_WAIT(1);
        } else {
            CP_WAIT(0);
        }
        __syncthreads();
        proj_compute(sb, (kc & 1) * PJ_STAGE, lane, wm, wn, acc);
        __syncthreads();
    }

    const float scale = (mode == 0) ? QSCALE : 1.0f;
    #pragma unroll
    for (int mt = 0; mt < 4; mt++)
        #pragma unroll
        for (int np = 0; np < 8; np++)
            #pragma unroll
            for (int h2 = 0; h2 < 2; h2++) {
                int m = m0 + wm + mt * 16 + (lane >> 2) + h2 * 8;
                int n = n0 + wn + np * 8 + 2 * (lane & 3);
                float v0 = (acc[mt][np][h2 * 2]     + bias[n])     * scale;
                float v1 = (acc[mt][np][h2 * 2 + 1] + bias[n + 1]) * scale;
                if (mode == 3) {
                    *(float2*)(Of + (size_t)m * DM + n) = make_float2(v0, v1);
                } else if (mode == 2) {
                    int bb = m >> 11, seq = m & 2047;
                    bf16 h0 = __float2bfloat16(v0), h1 = __float2bfloat16(v1);
                    size_t o0 = ((size_t)(bb * NH + (n >> 6)) * DH + (n & 63)) * SEQ + seq;
                    size_t o1 = ((size_t)(bb * NH + ((n+1) >> 6)) * DH + ((n+1) & 63)) * SEQ + seq;
                    Oh[o0] = h0; Ol[o0] = __float2bfloat16(v0 - __bfloat162float(h0));
                    Oh[o1] = h1; Ol[o1] = __float2bfloat16(v1 - __bfloat162float(h1));
                } else {
                    uint32_t hi, lo;
                    split2(v0, v1, hi, lo);
                    *(uint32_t*)(Oh + (size_t)m * DM + n) = hi;
                    *(uint32_t*)(Ol + (size_t)m * DM + n) = lo;
                }
            }
}

__global__ __launch_bounds__(256, 1) void qkv_proj_mma(const float* bq, const float* bk,
                                                       const float* bv) {
    extern __shared__ char sm[];
    const int z = blockIdx.z;
    proj_core(g_xh + (size_t)z * MTOT * DM, g_xl + (size_t)z * MTOT * DM,
              g_wth + (size_t)z * DM * DM, g_wtl + (size_t)z * DM * DM,
              (z == 0) ? bq : (z == 1) ? bk : bv,
              (z == 0) ? g_qh : (z == 1) ? g_kh : g_vth,
              (z == 0) ? g_ql : (z == 1) ? g_kl : g_vtl,
              nullptr, sm, blockIdx.y * 256, blockIdx.x * 128, z);
}

__global__ __launch_bounds__(256, 1) void out_proj_mma(const float* bo, float* out) {
    extern __shared__ char sm[];
    proj_core(g_zh, g_zl, g_woth, g_wotl, bo, nullptr, nullptr, out,
              sm, blockIdx.y * 256, blockIdx.x * 128, 3);
}

// ---------------- FA2 attention: pipelined S, 3 K/V stages ----------------
// CTA = (qb, head, batch), 256 threads, q-tile 128 (warp w: rows 16w), key-tile 64.
// smem: Q_hi@0 Q_lo@16K; stage s @ 32K+32K*s: K_hi 0, K_lo 8K, V_hi 16K, V_lo 24K. 128KB.
#define AT_ST0 32768
#define AT_SS  32768

__device__ __forceinline__ void attn_copy(uint32_t sb, int kb, int b, int hd, int t) {
    const int st = AT_ST0 + (kb % 3) * AT_SS;
    const int k0 = kb * 64;
    #pragma unroll
    for (int u = 0; u < 4; u++) {
        int idx = u * 256 + t;
        int sp = idx >> 9, row = (idx >> 3) & 63, c = idx & 7;
        uint32_t so = SWZ128((row << 7) + (c << 4));
        cpa16(sb + st + sp * 8192 + so,
              (sp ? g_kl : g_kh) + (size_t)(b * SEQ + k0 + row) * DM + hd * DH + c * 8);
        cpa16(sb + st + 16384 + sp * 8192 + so,
              (sp ? g_vtl : g_vth) + ((size_t)((b * NH + hd) * DH + row)) * SEQ + k0 + c * 8);
    }
}

__device__ __forceinline__ void attn_S(uint32_t sb, int st, int lane,
                                       const uint32_t qH[4][4], const uint32_t qL[4][4],
                                       float sacc[8][4])
{
    #pragma unroll
    for (int ds = 0; ds < 4; ds++)
        #pragma unroll
        for (int np = 0; np < 4; np++) {
            uint32_t kH[4], kL[4];
            ldsm4(kH, fraddr(sb + st,        lane, np * 16, 2 * ds));
            ldsm4(kL, fraddr(sb + st + 8192, lane, np * 16, 2 * ds));
            mma_bf16(sacc[2*np],   qH[ds], kH[0], kH[2]);
            mma_bf16(sacc[2*np+1], qH[ds], kH[1], kH[3]);
            mma_bf16(sacc[2*np],   qH[ds], kL[0], kL[2]);
            mma_bf16(sacc[2*np+1], qH[ds], kL[1], kL[3]);
            mma_bf16(sacc[2*np],   qL[ds], kH[0], kH[2]);
            mma_bf16(sacc[2*np+1], qL[ds], kH[1], kH[3]);
        }
}

__global__ __launch_bounds__(256, 1) void attn_mma() {
    extern __shared__ char sm[];
    const uint32_t sb = smem_u32(sm);
    const int t = threadIdx.x, lane = t & 31, w = t >> 5;
    const int qb = blockIdx.x, hd = blockIdx.y, b = blockIdx.z;
    const int q0 = qb * 128, wq = w * 16;
    const int nkb = 2 * qb + 2;

    attn_copy(sb, 0, b, hd, t);
    CP_COMMIT();
    attn_copy(sb, 1, b, hd, t);
    CP_COMMIT();

    // Q tile (128 x 64, hi/lo), plain stores
    {
        int r = t >> 1, s = t & 1;
        const bf16* __restrict__ src =
            (s ? g_ql : g_qh) + (size_t)(b * SEQ + q0 + r) * DM + hd * DH;
        char* dst = sm + (s ? 16384 : 0);
        #pragma unroll
        for (int i = 0; i < 8; i++)
            *(uint4*)(dst + SWZ128((r << 7) + (i << 4))) = *(const uint4*)(src + i * 8);
    }
    __syncthreads();

    uint32_t qH[4][4], qL[4][4];
    #pragma unroll
    for (int ks = 0; ks < 4; ks++) {
        ldsm4(qH[ks], fraddr(sb,         lane, wq, 2 * ks));
        ldsm4(qL[ks], fraddr(sb + 16384, lane, wq, 2 * ks));
    }

    float oacc[8][4] = {};
    float lsum[2] = {0.0f, 0.0f};

    // prologue: S(0)
    CP_WAIT(1);
    __syncthreads();
    float cur[8][4] = {};
    attn_S(sb, AT_ST0, lane, qH, qL, cur);

    for (int kb = 0; kb < nkb; kb++) {
        const int k0 = kb * 64;
        const int st = AT_ST0 + (kb % 3) * AT_SS;

        CP_WAIT(0);        // tile kb+1 resident
        __syncthreads();   // visible to all; stage (kb+2)%3 free for reuse
        if (kb + 2 < nkb) attn_copy(sb, kb + 2, b, hd, t);
        CP_COMMIT();

        // issue S(kb+1) first: independent HMMAs run under exp/split below
        float nxt[8][4] = {};
        if (kb + 1 < nkb)
            attn_S(sb, AT_ST0 + ((kb + 1) % 3) * AT_SS, lane, qH, qL, nxt);

        // exp + mask on cur (scores pre-scaled by log2e/8 via Q epilogue)
        if (kb >= 2 * qb) {
            #pragma unroll
            for (int np = 0; np < 8; np++)
                #pragma unroll
                for (int j = 0; j < 4; j++) {
                    int kg = k0 + np * 8 + 2 * (lane & 3) + (j & 1);
                    int qg = q0 + wq + (lane >> 2) + (j >> 1) * 8;
                    float p = (kg <= qg) ? ex2f(cur[np][j]) : 0.0f;
                    lsum[j >> 1] += p;
                    cur[np][j] = p;
                }
        } else {
            #pragma unroll
            for (int np = 0; np < 8; np++)
                #pragma unroll
                for (int j = 0; j < 4; j++) {
                    float p = ex2f(cur[np][j]);
                    lsum[j >> 1] += p;
                    cur[np][j] = p;
                }
        }

        // P (C-frag -> A-frag split) and PV from stage kb
        #pragma unroll
        for (int ks = 0; ks < 4; ks++) {
            uint32_t pH[4], pL[4];
            split2(cur[2*ks][0],   cur[2*ks][1],   pH[0], pL[0]);
            split2(cur[2*ks][2],   cur[2*ks][3],   pH[1], pL[1]);
            split2(cur[2*ks+1][0], cur[2*ks+1][1], pH[2], pL[2]);
            split2(cur[2*ks+1][2], cur[2*ks+1][3], pH[3], pL[3]);
            #pragma unroll
            for (int dp = 0; dp < 4; dp++) {
                uint32_t vH[4], vL[4];
                ldsm4(vH, fraddr(sb + st + 16384, lane, dp * 16, 2 * ks));
                ldsm4(vL, fraddr(sb + st + 24576, lane, dp * 16, 2 * ks));
                mma_bf16(oacc[2*dp],   pH, vH[0], vH[2]);
                mma_bf16(oacc[2*dp+1], pH, vH[1], vH[3]);
                mma_bf16(oacc[2*dp],   pH, vL[0], vL[2]);
                mma_bf16(oacc[2*dp+1], pH, vL[1], vL[3]);
                mma_bf16(oacc[2*dp],   pL, vH[0], vH[2]);
                mma_bf16(oacc[2*dp+1], pL, vH[1], vH[3]);
            }
        }

        #pragma unroll
        for (int np = 0; np < 8; np++)
            #pragma unroll
            for (int j = 0; j < 4; j++)
                cur[np][j] = nxt[np][j];
    }

    #pragma unroll
    for (int i = 0; i < 2; i++) {
        lsum[i] += __shfl_xor_sync(0xffffffffu, lsum[i], 1);
        lsum[i] += __shfl_xor_sync(0xffffffffu, lsum[i], 2);
    }
    float inv0 = 1.0f / lsum[0], inv1 = 1.0f / lsum[1];

    #pragma unroll
    for (int np = 0; np < 8; np++)
        #pragma unroll
        for (int h2 = 0; h2 < 2; h2++) {
            int q = q0 + wq + (lane >> 2) + h2 * 8;
            int d = np * 8 + 2 * (lane & 3);
            float inv = h2 ? inv1 : inv0;
            float v0 = oacc[np][h2 * 2] * inv;
            float v1 = oacc[np][h2 * 2 + 1] * inv;
            uint32_t hi, lo;
            split2(v0, v1, hi, lo);
            size_t o = (size_t)(b * SEQ + q) * DM + hd * DH + d;
            *(uint32_t*)(g_zh + o) = hi;
            *(uint32_t*)(g_zl + o) = lo;
        }
}

// ---------------------------------------------------------------------------
extern "C" void kernel_launch(void* const* d_in, const int* in_sizes, int n_in,
                              void* d_out, int out_size)
{
    const float* qin = (const float*)d_in[0];
    const float* kin = (const float*)d_in[1];
    const float* vin = (const float*)d_in[2];
    const float* WQ  = (const float*)d_in[3];
    const float* WK  = (const float*)d_in[4];
    const float* WV  = (const float*)d_in[5];
    const float* WO  = (const float*)d_in[6];
    const float* bQ  = (const float*)d_in[7];
    const float* bK  = (const float*)d_in[8];
    const float* bV  = (const float*)d_in[9];
    const float* bO  = (const float*)d_in[10];
    float* out = (float*)d_out;

    cudaFuncSetAttribute(qkv_proj_mma, cudaFuncAttributeMaxDynamicSharedMemorySize, 196608);
    cudaFuncSetAttribute(out_proj_mma, cudaFuncAttributeMaxDynamicSharedMemorySize, 196608);
    cudaFuncSetAttribute(attn_mma,     cudaFuncAttributeMaxDynamicSharedMemorySize, 131072);

    cvt_x_kernel<<<dim3(MTOT * DM / 8 / 256, 3), 256>>>(qin, kin, vin);
    cvt_wqkv_kernel<<<dim3(32, 2, 48), dim3(32, 8)>>>(WQ, WK, WV);
    cvt_wo_kernel<<<dim3(32, 32), dim3(32, 8)>>>(WO);

    qkv_proj_mma<<<dim3(DM / 128, MTOT / 256, 3), 256, 196608>>>(bQ, bK, bV);
    attn_mma<<<dim3(SEQ / 128, NH, BATCH), 256, 131072>>>();
    out_proj_mma<<<dim3(DM / 128, MTOT / 256), 256, 196608>>>(bO, out);
}